// round 5
// baseline (speedup 1.0000x reference)
#include <cuda_runtime.h>
#include <cstdint>

// naivePC: DP over (k,m) lattice, K=8, N=20.
// S(k,m) = w0[k][m]*S(k,m-1) + w1[k][m]*S(k-1,m-1)*x[m-1],  S(k,k)=prod first k bits.
// Leaf collapse: S(1,j) nonzero only for j in (p1,p2]; consumed by k=2 only at
// j=p2 (the only set bit there) => single injection v=w1_2[p2+1]*wsm[p2][p1] at
// column mstart=p2+1, after which S(2,m) = c*P2[m] (pure decay, P2 row-uniform).
// k=3 update becomes: S3 = w0_3[m]*S3 + q * fma(c, g3[m], .), g3[m]=w1_3[m]*P2[m-1],
// q = bit(m-1) && (m-1 >= mstart)  (precomputed bitmask Q).

#define NCOL 20
#define KMAX 8
#define RPT 2
#define THREADS 256
#define ROWS_PER_BLOCK (THREADS * RPT)   // 512

__global__ __launch_bounds__(THREADS, 6)
void pc_kernel(const unsigned char* __restrict__ xb,
               const float* __restrict__ Wleaf,   // [21][20]
               const float* __restrict__ W2,      // [9][21][2]
               float* __restrict__ out,
               int B)
{
    __shared__ float  s_wsm[21 * 32];     // stride 32: conflict-free dynamic gather
    __shared__ float2 s_w01[9 * 21];      // (w0,w1) pairs
    __shared__ float  s_P2[21];           // prod_{j=3..m} w0_2[j], P2[2]=1
    __shared__ float  s_invP2[22];        // 1/P2, [21]=0 sentinel
    __shared__ float  s_g3[21];           // w1_3[m]*P2[m-1]
    __shared__ int    s_elem4;
    __shared__ uint4  s_stage[THREADS * 5];   // 20KB staging (one 256-row chunk)

    const int tid = threadIdx.x;

    // ---- phase A: softmax tables (per block; tiny) ----
    if (tid < 21) {
        int m = tid;
        float mx = -1e30f;
        for (int i = 0; i < m; i++) mx = fmaxf(mx, Wleaf[m * 20 + i]);
        float Z = 0.0f;
        for (int i = 0; i < m; i++) Z += expf(Wleaf[m * 20 + i] - mx);
        float inv = (m > 0) ? (1.0f / Z) : 0.0f;
        for (int i = 0; i < 32; i++) {
            float v = 0.0f;
            if (i < m) v = expf(Wleaf[m * 20 + i] - mx) * inv;
            s_wsm[m * 32 + i] = v;
        }
    }
    if (tid >= 32 && tid < 32 + 9 * 21) {
        int j = tid - 32;
        float a = W2[j * 2 + 0];
        float b = W2[j * 2 + 1];
        float mx = fmaxf(a, b);
        float e0 = expf(a - mx), e1 = expf(b - mx);
        float inv = 1.0f / (e0 + e1);
        s_w01[j] = make_float2(e0 * inv, e1 * inv);
    }
    // ---- dtype detection from first 128 bytes (warp 7; L2-hit everywhere) ----
    if (tid >= 224) {
        int lane = tid - 224;
        unsigned w = reinterpret_cast<const unsigned*>(xb)[lane];
        unsigned gt1 = __ballot_sync(0xFFFFFFFFu, (w & 0xFEFEFEFEu) != 0u); // byte>1 -> 4-byte elems
        unsigned hi  = __ballot_sync(0xFFFFFFFFu, (w & 0xFFFFFF00u) != 0u); // upper bytes nz -> bool
        if (lane == 0) s_elem4 = (gt1 != 0u || hi == 0u) ? 1 : 0;
    }
    __syncthreads();

    // ---- phase B: derived row-uniform tables ----
    if (tid < 21) {
        int m = tid;
        float p = 1.0f;
        for (int j = 3; j <= m; j++) p *= s_w01[2 * 21 + j].x;
        if (m >= 2) { s_P2[m] = p; s_invP2[m] = 1.0f / p; }
        else        { s_P2[m] = 0.0f; s_invP2[m] = 0.0f; }
        float pm1 = (m >= 3) ? ((m - 1 >= 3) ? p / s_w01[2 * 21 + m].x : 1.0f) : 0.0f;
        s_g3[m] = (m >= 4) ? s_w01[3 * 21 + m].y * pm1 : 0.0f;
        if (m == 0) s_invP2[21] = 0.0f;
    }
    __syncthreads();

    const int elem4 = s_elem4;
    const long rowBase = (long)blockIdx.x * ROWS_PER_BLOCK;
    const bool fullBlock = (rowBase + ROWS_PER_BLOCK) <= (long)B;

    // ---- build 20-bit masks; thread owns rows rowBase + ch*256 + tid ----
    unsigned mask[RPT] = {0, 0};

    if (elem4 && fullBlock) {
        #pragma unroll
        for (int ch = 0; ch < RPT; ch++) {
            const uint4* src = reinterpret_cast<const uint4*>(xb) + (rowBase + (long)ch * THREADS) * 5;
            #pragma unroll
            for (int j = 0; j < 5; j++)
                s_stage[tid + THREADS * j] = src[tid + THREADS * j];
            __syncthreads();
            unsigned mres = 0;
            #pragma unroll
            for (int j = 0; j < 5; j++) {
                uint4 q = s_stage[tid * 5 + j];
                // min(w,1) maps {0->0, 1->1, 0x3F800000->1}: works for float32 and int32
                unsigned n = min(q.x, 1u) + min(q.y, 1u) * 2u + min(q.z, 1u) * 4u + min(q.w, 1u) * 8u;
                mres += n << (4 * j);
            }
            mask[ch] = mres;
            __syncthreads();
        }
    } else if (!elem4 && fullBlock) {
        // bool bytes: block covers 512 rows * 20B = 10KB = 640 uint4
        for (int i = tid; i < ROWS_PER_BLOCK * 20 / 16; i += THREADS)
            s_stage[i] = reinterpret_cast<const uint4*>(xb + rowBase * 20)[i];
        __syncthreads();
        const unsigned* sw = reinterpret_cast<const unsigned*>(s_stage);
        #pragma unroll
        for (int r = 0; r < RPT; r++) {
            int rl = r * THREADS + tid;
            unsigned mres = 0;
            #pragma unroll
            for (int j = 0; j < 5; j++) {
                unsigned b = sw[rl * 5 + j] & 0x01010101u;
                unsigned nib = ((b * 0x01020408u) >> 24) & 0xFu;
                mres |= nib << (4 * j);
            }
            mask[r] = mres;
        }
        __syncthreads();
    } else {
        #pragma unroll
        for (int r = 0; r < RPT; r++) {
            long row = rowBase + (long)r * THREADS + tid;
            unsigned mres = 0;
            if (row < (long)B) {
                if (elem4) {
                    const unsigned* p = reinterpret_cast<const unsigned*>(xb);
                    for (int m = 0; m < 20; m++)
                        mres |= (unsigned)(min(p[row * 20 + m], 1u)) << m;
                } else {
                    for (int m = 0; m < 20; m++)
                        mres |= (unsigned)(xb[row * 20 + m] & 1) << m;
                }
            }
            mask[r] = mres;
        }
    }

    // ---- per-row one-time leaf/k2 collapse ----
    float cc[RPT];
    unsigned Q[RPT];
    #pragma unroll
    for (int r = 0; r < RPT; r++) {
        unsigned M = mask[r];
        unsigned rem = M & (M - 1);
        int mst;
        float v;
        if (rem != 0u) {
            int p1 = __ffs(M) - 1;
            int p2 = __ffs(rem) - 1;
            mst = p2 + 1;
            bool pf2 = (M & 3u) == 3u;
            v = pf2 ? 1.0f : s_w01[2 * 21 + mst].y * s_wsm[p2 * 32 + p1];
        } else {
            mst = 21;
            v = 0.0f;
        }
        cc[r] = v * s_invP2[mst];
        Q[r]  = M & (0xFFFFFFFFu << mst);
    }

    // ---- column-sweep DP, levels k=3..8 only ----
    float S[RPT][KMAX - 2];   // S[r][k-3]
    #pragma unroll
    for (int r = 0; r < RPT; r++)
        #pragma unroll
        for (int k = 0; k < KMAX - 2; k++) S[r][k] = 0.0f;

    #pragma unroll
    for (int m = 1; m <= NCOL; m++) {
        unsigned bit[RPT], qb[RPT];
        #pragma unroll
        for (int r = 0; r < RPT; r++) {
            bit[r] = (mask[r] >> (m - 1)) & 1u;
            qb[r]  = (Q[r]    >> (m - 1)) & 1u;
        }
        #pragma unroll
        for (int k = KMAX; k >= 4; k--) {
            if (k > m) continue;                    // folds at compile time
            if (k == m) {
                const unsigned km = (1u << k) - 1u;
                #pragma unroll
                for (int r = 0; r < RPT; r++)
                    S[r][k - 3] = ((mask[r] & km) == km) ? 1.0f : 0.0f;
            } else {
                const float2 w = s_w01[k * 21 + m];
                #pragma unroll
                for (int r = 0; r < RPT; r++) {
                    float u = w.x * S[r][k - 3];
                    S[r][k - 3] = bit[r] ? fmaf(w.y, S[r][k - 4], u) : u;
                }
            }
        }
        if (m == 3) {
            #pragma unroll
            for (int r = 0; r < RPT; r++)
                S[r][0] = ((mask[r] & 7u) == 7u) ? 1.0f : 0.0f;
        } else if (m > 3) {
            const float w03 = s_w01[3 * 21 + m].x;
            const float g3m = s_g3[m];
            #pragma unroll
            for (int r = 0; r < RPT; r++) {
                float u = w03 * S[r][0];
                S[r][0] = qb[r] ? fmaf(cc[r], g3m, u) : u;
            }
        }
    }

    #pragma unroll
    for (int r = 0; r < RPT; r++) {
        long row = rowBase + (long)r * THREADS + tid;
        if (row < (long)B) out[row] = S[r][KMAX - 3];
    }
}

extern "C" void kernel_launch(void* const* d_in, const int* in_sizes, int n_in,
                              void* d_out, int out_size)
{
    const unsigned char* x = (const unsigned char*)d_in[0];
    const float* Wleaf = (const float*)d_in[1];
    const float* W2 = (const float*)d_in[2];
    float* out = (float*)d_out;

    const int B = in_sizes[0] / NCOL;
    const int blocks = (B + ROWS_PER_BLOCK - 1) / ROWS_PER_BLOCK;

    pc_kernel<<<blocks, THREADS>>>(x, Wleaf, W2, out, B);
}

// round 6
// speedup vs baseline: 1.0617x; 1.0617x over previous
#include <cuda_runtime.h>
#include <cstdint>

// naivePC: DP over (k,m) lattice, K=8, N=20.
// S(k,m) = w0[k][m]*S(k,m-1) + w1[k][m]*S(k-1,m-1)*x[m-1],  S(k,k)=prod first k bits.
// Leaf collapse: S(1,j) nonzero only for j in (p1,p2]; consumed by k=2 only at
// j=p2 => single injection v=w1_2[p2+1]*wsm[p2][p1] at column mstart=p2+1, after
// which S(2,m)=c*P2[m] (row-uniform decay). k=3 update uses g3[m]=w1_3[m]*P2[m-1]
// and bitmask Q = mask & (~0 << mstart).

#define NCOL 20
#define KMAX 8
#define RPT 4
#define THREADS 256
#define ROWS_PER_BLOCK (THREADS * RPT)   // 1024

// ---- precomputed tables (written by prep_kernel) ----
__device__ float  g_wsm[21 * 32];
__device__ float2 g_w01[9 * 21];
__device__ float  g_invP2[22];
__device__ float  g_g3[21];
__device__ int    g_elem4;

__global__ void prep_kernel(const unsigned char* __restrict__ xb,
                            const float* __restrict__ Wleaf,
                            const float* __restrict__ W2)
{
    const int tid = threadIdx.x;
    if (tid < 21) {
        int m = tid;
        float mx = -1e30f;
        for (int i = 0; i < m; i++) mx = fmaxf(mx, Wleaf[m * 20 + i]);
        float Z = 0.0f;
        for (int i = 0; i < m; i++) Z += expf(Wleaf[m * 20 + i] - mx);
        float inv = (m > 0) ? (1.0f / Z) : 0.0f;
        for (int i = 0; i < 32; i++) {
            float v = 0.0f;
            if (i < m) v = expf(Wleaf[m * 20 + i] - mx) * inv;
            g_wsm[m * 32 + i] = v;
        }
    }
    if (tid >= 32 && tid < 32 + 9 * 21) {
        int j = tid - 32;
        float a = W2[j * 2 + 0];
        float b = W2[j * 2 + 1];
        float mx = fmaxf(a, b);
        float e0 = expf(a - mx), e1 = expf(b - mx);
        float inv = 1.0f / (e0 + e1);
        g_w01[j] = make_float2(e0 * inv, e1 * inv);
    }
    if (tid >= 224) {   // dtype detection from first 128 bytes
        int lane = tid - 224;
        unsigned w = reinterpret_cast<const unsigned*>(xb)[lane];
        unsigned gt1 = __ballot_sync(0xFFFFFFFFu, (w & 0xFEFEFEFEu) != 0u);
        unsigned hi  = __ballot_sync(0xFFFFFFFFu, (w & 0xFFFFFF00u) != 0u);
        if (lane == 0) g_elem4 = (gt1 != 0u || hi == 0u) ? 1 : 0;
    }
    __syncthreads();
    if (tid < 22) {
        int m = tid;
        if (m < 21) {
            float p = 1.0f;
            for (int j = 3; j <= m; j++) p *= g_w01[2 * 21 + j].x;
            g_invP2[m] = (m >= 2) ? (1.0f / p) : 0.0f;
            float pm1 = (m >= 3) ? p / g_w01[2 * 21 + m].x : 0.0f;
            g_g3[m] = (m >= 4) ? g_w01[3 * 21 + m].y * pm1 : 0.0f;
        } else {
            g_invP2[21] = 0.0f;
        }
    }
}

__global__ __launch_bounds__(THREADS, 5)
void pc_kernel(const unsigned char* __restrict__ xb,
               float* __restrict__ out,
               int B)
{
    __shared__ float  s_wsm[21 * 32];
    __shared__ float2 s_w01[9 * 21];
    __shared__ float  s_invP2[22];
    __shared__ float  s_g3[21];
    __shared__ uint4  s_stage[THREADS * 5];   // 20KB: one 256-row chunk (elem4) / 1024 bool rows

    const int tid = threadIdx.x;

    // ---- fast table copy from precomputed globals (coalesced) ----
    for (int i = tid; i < 21 * 32; i += THREADS) s_wsm[i] = g_wsm[i];
    if (tid < 9 * 21) s_w01[tid] = g_w01[tid];
    else if (tid >= 192 && tid < 192 + 22) s_invP2[tid - 192] = g_invP2[tid - 192];
    else if (tid >= 224 && tid < 224 + 21) s_g3[tid - 224] = g_g3[tid - 224];
    const int elem4 = g_elem4;
    __syncthreads();

    const long rowBase = (long)blockIdx.x * ROWS_PER_BLOCK;
    const bool fullBlock = (rowBase + ROWS_PER_BLOCK) <= (long)B;

    // ---- build 20-bit masks; thread owns rows rowBase + ch*256 + tid ----
    unsigned mask[RPT] = {0, 0, 0, 0};

    if (elem4 && fullBlock) {
        #pragma unroll
        for (int ch = 0; ch < RPT; ch++) {
            const uint4* src = reinterpret_cast<const uint4*>(xb) + (rowBase + (long)ch * THREADS) * 5;
            #pragma unroll
            for (int j = 0; j < 5; j++)
                s_stage[tid + THREADS * j] = src[tid + THREADS * j];
            __syncthreads();
            unsigned mres = 0;
            #pragma unroll
            for (int j = 0; j < 5; j++) {
                uint4 q = s_stage[tid * 5 + j];
                // min(w,1) maps {0,1,0x3F800000} -> {0,1,1}: float32 & int32 safe
                unsigned n = min(q.x, 1u) + min(q.y, 1u) * 2u + min(q.z, 1u) * 4u + min(q.w, 1u) * 8u;
                mres += n << (4 * j);
            }
            mask[ch] = mres;
            __syncthreads();
        }
    } else if (!elem4 && fullBlock) {
        // bool bytes: 1024 rows * 20B = 20KB = 1280 uint4
        for (int i = tid; i < ROWS_PER_BLOCK * 20 / 16; i += THREADS)
            s_stage[i] = reinterpret_cast<const uint4*>(xb + rowBase * 20)[i];
        __syncthreads();
        const unsigned* sw = reinterpret_cast<const unsigned*>(s_stage);
        #pragma unroll
        for (int r = 0; r < RPT; r++) {
            int rl = r * THREADS + tid;
            unsigned mres = 0;
            #pragma unroll
            for (int j = 0; j < 5; j++) {
                unsigned b = sw[rl * 5 + j] & 0x01010101u;
                unsigned nib = ((b * 0x01020408u) >> 24) & 0xFu;
                mres |= nib << (4 * j);
            }
            mask[r] = mres;
        }
        __syncthreads();
    } else {
        #pragma unroll
        for (int r = 0; r < RPT; r++) {
            long row = rowBase + (long)r * THREADS + tid;
            unsigned mres = 0;
            if (row < (long)B) {
                if (elem4) {
                    const unsigned* p = reinterpret_cast<const unsigned*>(xb);
                    for (int m = 0; m < 20; m++)
                        mres |= (unsigned)(min(p[row * 20 + m], 1u)) << m;
                } else {
                    for (int m = 0; m < 20; m++)
                        mres |= (unsigned)(xb[row * 20 + m] & 1) << m;
                }
            }
            mask[r] = mres;
        }
    }

    // ---- per-row one-time leaf/k2 collapse ----
    float cc[RPT];
    unsigned Q[RPT];
    #pragma unroll
    for (int r = 0; r < RPT; r++) {
        unsigned M = mask[r];
        unsigned rem = M & (M - 1);
        int mst;
        float v;
        if (rem != 0u) {
            int p1 = __ffs(M) - 1;
            int p2 = __ffs(rem) - 1;
            mst = p2 + 1;
            bool pf2 = (M & 3u) == 3u;
            v = pf2 ? 1.0f : s_w01[2 * 21 + mst].y * s_wsm[p2 * 32 + p1];
        } else {
            mst = 21;
            v = 0.0f;
        }
        cc[r] = v * s_invP2[mst];
        Q[r]  = M & (0xFFFFFFFFu << mst);
    }

    // ---- column-sweep DP, levels k=3..8 only ----
    float S[RPT][KMAX - 2];   // S[r][k-3]
    #pragma unroll
    for (int r = 0; r < RPT; r++)
        #pragma unroll
        for (int k = 0; k < KMAX - 2; k++) S[r][k] = 0.0f;

    #pragma unroll
    for (int m = 1; m <= NCOL; m++) {
        unsigned bit[RPT], qb[RPT];
        #pragma unroll
        for (int r = 0; r < RPT; r++) {
            bit[r] = (mask[r] >> (m - 1)) & 1u;
            qb[r]  = (Q[r]    >> (m - 1)) & 1u;
        }
        #pragma unroll
        for (int k = KMAX; k >= 4; k--) {
            if (k > m) continue;                    // folds at compile time
            if (k == m) {
                const unsigned km = (1u << k) - 1u;
                #pragma unroll
                for (int r = 0; r < RPT; r++)
                    S[r][k - 3] = ((mask[r] & km) == km) ? 1.0f : 0.0f;
            } else {
                const float2 w = s_w01[k * 21 + m];
                #pragma unroll
                for (int r = 0; r < RPT; r++) {
                    float u = w.x * S[r][k - 3];
                    S[r][k - 3] = bit[r] ? fmaf(w.y, S[r][k - 4], u) : u;
                }
            }
        }
        if (m == 3) {
            #pragma unroll
            for (int r = 0; r < RPT; r++)
                S[r][0] = ((mask[r] & 7u) == 7u) ? 1.0f : 0.0f;
        } else if (m > 3) {
            const float w03 = s_w01[3 * 21 + m].x;
            const float g3m = s_g3[m];
            #pragma unroll
            for (int r = 0; r < RPT; r++) {
                float u = w03 * S[r][0];
                S[r][0] = qb[r] ? fmaf(cc[r], g3m, u) : u;
            }
        }
    }

    #pragma unroll
    for (int r = 0; r < RPT; r++) {
        long row = rowBase + (long)r * THREADS + tid;
        if (row < (long)B) out[row] = S[r][KMAX - 3];
    }
}

extern "C" void kernel_launch(void* const* d_in, const int* in_sizes, int n_in,
                              void* d_out, int out_size)
{
    const unsigned char* x = (const unsigned char*)d_in[0];
    const float* Wleaf = (const float*)d_in[1];
    const float* W2 = (const float*)d_in[2];
    float* out = (float*)d_out;

    const int B = in_sizes[0] / NCOL;
    const int blocks = (B + ROWS_PER_BLOCK - 1) / ROWS_PER_BLOCK;

    prep_kernel<<<1, 256>>>(x, Wleaf, W2);
    pc_kernel<<<blocks, THREADS>>>(x, out, B);
}

// round 9
// speedup vs baseline: 1.1750x; 1.1067x over previous
#include <cuda_runtime.h>
#include <cstdint>

// naivePC: DP over (k,m) lattice, K=8, N=20.
// S(k,m) = w0[k][m]*S(k,m-1) + w1[k][m]*S(k-1,m-1)*x[m-1],  S(k,k)=prod first k bits.
// Leaf collapse (validated R5/R6): single injection at mstart=p2+1 with
// c = v/P2[mstart], v = w1_2[mstart]*wsm[p2][p1]  (or 1 if bits 0,1 both set);
// k=3 update uses g3[m] = w1_3[m]*P2[m-1] and Q = mask & (~0 << mstart).

#define NCOL 20
#define KMAX 8
#define TILES 2                       // 32-row tiles per warp
#define THREADS 128
#define WARPS (THREADS / 32)
#define ROWS_PER_BLOCK (THREADS * TILES)   // 256

// ---- precomputed tables (written by prep_kernel) ----
__device__ float  g_wsm[21 * 32];
__device__ float2 g_w01[9 * 21];
__device__ float  g_invP2[22];
__device__ float  g_g3[21];
__device__ int    g_elem4;

__global__ void prep_kernel(const unsigned char* __restrict__ xb,
                            const float* __restrict__ Wleaf,
                            const float* __restrict__ W2)
{
    const int tid = threadIdx.x;
    if (tid < 21) {
        int m = tid;
        float mx = -1e30f;
        for (int i = 0; i < m; i++) mx = fmaxf(mx, Wleaf[m * 20 + i]);
        float Z = 0.0f;
        for (int i = 0; i < m; i++) Z += expf(Wleaf[m * 20 + i] - mx);
        float inv = (m > 0) ? (1.0f / Z) : 0.0f;
        for (int i = 0; i < 32; i++) {
            float v = 0.0f;
            if (i < m) v = expf(Wleaf[m * 20 + i] - mx) * inv;
            g_wsm[m * 32 + i] = v;
        }
    }
    if (tid >= 32 && tid < 32 + 9 * 21) {
        int j = tid - 32;
        float a = W2[j * 2 + 0];
        float b = W2[j * 2 + 1];
        float mx = fmaxf(a, b);
        float e0 = expf(a - mx), e1 = expf(b - mx);
        float inv = 1.0f / (e0 + e1);
        g_w01[j] = make_float2(e0 * inv, e1 * inv);
    }
    if (tid >= 224) {   // dtype detection from first 128 bytes
        int lane = tid - 224;
        unsigned w = reinterpret_cast<const unsigned*>(xb)[lane];
        unsigned gt1 = __ballot_sync(0xFFFFFFFFu, (w & 0xFEFEFEFEu) != 0u);
        unsigned hi  = __ballot_sync(0xFFFFFFFFu, (w & 0xFFFFFF00u) != 0u);
        if (lane == 0) g_elem4 = (gt1 != 0u || hi == 0u) ? 1 : 0;
    }
    __syncthreads();
    if (tid < 22) {
        int m = tid;
        if (m < 21) {
            float p = 1.0f;
            for (int j = 3; j <= m; j++) p *= g_w01[2 * 21 + j].x;
            g_invP2[m] = (m >= 2) ? (1.0f / p) : 0.0f;
            float pm1 = (m >= 3) ? p / g_w01[2 * 21 + m].x : 0.0f;
            g_g3[m] = (m >= 4) ? g_w01[3 * 21 + m].y * pm1 : 0.0f;
        } else {
            g_invP2[21] = 0.0f;
        }
    }
}

__global__ __launch_bounds__(THREADS, 12)
void pc_kernel(const unsigned char* __restrict__ xb,
               float* __restrict__ out,
               int B)
{
    __shared__ float2   s_w01[9 * 21];
    __shared__ float    s_g3[21];
    __shared__ unsigned s_bal[WARPS][24];   // 20 ballot words + pad

    const int tid    = threadIdx.x;
    const int lane   = tid & 31;
    const int warpId = tid >> 5;

    // ---- tiny table copy (w01, g3) ----
    for (int i = tid; i < 9 * 21; i += THREADS) s_w01[i] = g_w01[i];
    if (tid < 21) s_g3[tid] = g_g3[tid];
    const int elem4 = g_elem4;
    __syncthreads();

    const long blockRow = (long)blockIdx.x * ROWS_PER_BLOCK;
    const long warpRow  = blockRow + (long)warpId * (32 * TILES);

    // ---- build masks: ballot transpose, one 32-row tile at a time ----
    unsigned mask[TILES];

    if (elem4) {
        const unsigned* xw = reinterpret_cast<const unsigned*>(xb);
        const long wTotal = (long)B * 20;
        #pragma unroll
        for (int t = 0; t < TILES; t++) {
            const long tileRow = warpRow + (long)t * 32;
            const long wbase = tileRow * 20;
            if (tileRow + 32 <= (long)B) {
                #pragma unroll
                for (int j = 0; j < 20; j++) {
                    unsigned w = xw[wbase + j * 32 + lane];
                    unsigned bal = __ballot_sync(0xFFFFFFFFu, w != 0u);
                    if (lane == 0) s_bal[warpId][j] = bal;
                }
            } else {
                #pragma unroll
                for (int j = 0; j < 20; j++) {
                    long idx = wbase + j * 32 + lane;
                    unsigned w = (idx < wTotal) ? xw[idx] : 0u;
                    unsigned bal = __ballot_sync(0xFFFFFFFFu, w != 0u);
                    if (lane == 0) s_bal[warpId][j] = bal;
                }
            }
            __syncwarp();
            int pos = 20 * lane;
            unsigned lo = s_bal[warpId][pos >> 5];
            unsigned hi = s_bal[warpId][(pos >> 5) + 1];
            mask[t] = __funnelshift_r(lo, hi, pos & 31) & 0xFFFFFu;
            __syncwarp();
        }
    } else {
        // bool bytes: each lane reads its own row (correct, rarely taken)
        #pragma unroll
        for (int t = 0; t < TILES; t++) {
            long row = warpRow + (long)t * 32 + lane;
            unsigned mres = 0;
            if (row < (long)B) {
                const unsigned* p = reinterpret_cast<const unsigned*>(xb + row * 20);
                #pragma unroll
                for (int j = 0; j < 5; j++) {
                    unsigned b = p[j] & 0x01010101u;
                    unsigned nib = ((b * 0x01020408u) >> 24) & 0xFu;
                    mres |= nib << (4 * j);
                }
            }
            mask[t] = mres;
        }
    }

    // ---- per-row one-time leaf/k2 collapse ----
    float cc[TILES];
    unsigned Q[TILES];
    #pragma unroll
    for (int r = 0; r < TILES; r++) {
        unsigned M = mask[r];
        unsigned rem = M & (M - 1);
        int mst;
        float v;
        if (rem != 0u) {
            int p1 = __ffs(M) - 1;
            int p2 = __ffs(rem) - 1;
            mst = p2 + 1;
            bool pf2 = (M & 3u) == 3u;
            v = pf2 ? 1.0f : __ldg(&((const float*)g_w01)[(2 * 21 + mst) * 2 + 1])
                           * __ldg(&g_wsm[p2 * 32 + p1]);
        } else {
            mst = 21;
            v = 0.0f;
        }
        cc[r] = v * __ldg(&g_invP2[mst]);
        Q[r]  = M & (0xFFFFFFFFu << mst);
    }

    // ---- column-sweep DP, levels k=3..8 only ----
    float S[TILES][KMAX - 2];   // S[r][k-3]
    #pragma unroll
    for (int r = 0; r < TILES; r++)
        #pragma unroll
        for (int k = 0; k < KMAX - 2; k++) S[r][k] = 0.0f;

    #pragma unroll
    for (int m = 1; m <= NCOL; m++) {
        unsigned bit[TILES], qb[TILES];
        #pragma unroll
        for (int r = 0; r < TILES; r++) {
            bit[r] = (mask[r] >> (m - 1)) & 1u;
            qb[r]  = (Q[r]    >> (m - 1)) & 1u;
        }
        #pragma unroll
        for (int k = KMAX; k >= 4; k--) {
            if (k > m) continue;                    // folds at compile time
            if (k == m) {
                const unsigned km = (1u << k) - 1u;
                #pragma unroll
                for (int r = 0; r < TILES; r++)
                    S[r][k - 3] = ((mask[r] & km) == km) ? 1.0f : 0.0f;
            } else {
                const float2 w = s_w01[k * 21 + m];
                #pragma unroll
                for (int r = 0; r < TILES; r++) {
                    float u = w.x * S[r][k - 3];
                    S[r][k - 3] = bit[r] ? fmaf(w.y, S[r][k - 4], u) : u;
                }
            }
        }
        if (m == 3) {
            #pragma unroll
            for (int r = 0; r < TILES; r++)
                S[r][0] = ((mask[r] & 7u) == 7u) ? 1.0f : 0.0f;
        } else if (m > 3) {
            const float w03 = s_w01[3 * 21 + m].x;
            const float g3m = s_g3[m];
            #pragma unroll
            for (int r = 0; r < TILES; r++) {
                float u = w03 * S[r][0];
                S[r][0] = qb[r] ? fmaf(cc[r], g3m, u) : u;
            }
        }
    }

    // ---- coalesced store: lane owns row warpRow + t*32 + lane ----
    #pragma unroll
    for (int t = 0; t < TILES; t++) {
        long row = warpRow + (long)t * 32 + lane;
        if (row < (long)B) out[row] = S[t][KMAX - 3];
    }
}

extern "C" void kernel_launch(void* const* d_in, const int* in_sizes, int n_in,
                              void* d_out, int out_size)
{
    const unsigned char* x = (const unsigned char*)d_in[0];
    const float* Wleaf = (const float*)d_in[1];
    const float* W2 = (const float*)d_in[2];
    float* out = (float*)d_out;

    const int B = in_sizes[0] / NCOL;
    const int blocks = (B + ROWS_PER_BLOCK - 1) / ROWS_PER_BLOCK;

    prep_kernel<<<1, 256>>>(x, Wleaf, W2);
    pc_kernel<<<blocks, THREADS>>>(x, out, B);
}

// round 10
// speedup vs baseline: 1.3532x; 1.1516x over previous
#include <cuda_runtime.h>
#include <cstdint>

// naivePC: DP over (k,m) lattice, K=8, N=20.
// S(k,m) = w0[k][m]*S(k,m-1) + w1[k][m]*S(k-1,m-1)*x[m-1],  S(k,k)=prod first k bits.
// Leaf collapse: single injection at mstart=p2+1 with c = v/P2[mstart],
// v = w1_2[mstart]*wsm[p2][p1] (or 1 if bits 0,1 set); k=3 uses g3[m]=w1_3[m]*P2[m-1],
// Q = mask & (~0 << mstart).

#define NCOL 20
#define KMAX 8
#define TILES 2
#define THREADS 128
#define WARPS (THREADS / 32)
#define ROWS_PER_BLOCK (THREADS * TILES)   // 256

__device__ float  g_wsm[21 * 32];
__device__ float2 g_w01[9 * 21];
__device__ float  g_invP2[22];
__device__ float  g_g3[21];
__device__ int    g_elem4;

__global__ void prep_kernel(const unsigned char* __restrict__ xb,
                            const float* __restrict__ Wleaf,
                            const float* __restrict__ W2)
{
    const int tid  = threadIdx.x;
    const int lane = tid & 31;
    const int wid  = tid >> 5;

    // ---- wsm: one warp per m, shuffle reductions ----
    if (wid < 21) {
        int m = wid;
        float v = (lane < m) ? Wleaf[m * 20 + lane] : -1e30f;
        float mx = v;
        #pragma unroll
        for (int o = 16; o > 0; o >>= 1) mx = fmaxf(mx, __shfl_xor_sync(0xFFFFFFFFu, mx, o));
        float e = (lane < m) ? expf(v - mx) : 0.0f;
        float Z = e;
        #pragma unroll
        for (int o = 16; o > 0; o >>= 1) Z += __shfl_xor_sync(0xFFFFFFFFu, Z, o);
        float inv = (m > 0) ? (1.0f / Z) : 0.0f;
        g_wsm[m * 32 + lane] = e * inv;
    }
    // ---- w2 softmax: 189 pairs ----
    if (tid < 9 * 21) {
        float a = W2[tid * 2 + 0];
        float b = W2[tid * 2 + 1];
        float mx = fmaxf(a, b);
        float e0 = expf(a - mx), e1 = expf(b - mx);
        float inv = 1.0f / (e0 + e1);
        g_w01[tid] = make_float2(e0 * inv, e1 * inv);
    }
    // ---- dtype detection (warp 21) ----
    if (wid == 21) {
        unsigned w = reinterpret_cast<const unsigned*>(xb)[lane];
        unsigned gt1 = __ballot_sync(0xFFFFFFFFu, (w & 0xFEFEFEFEu) != 0u);
        unsigned hi  = __ballot_sync(0xFFFFFFFFu, (w & 0xFFFFFF00u) != 0u);
        if (lane == 0) g_elem4 = (gt1 != 0u || hi == 0u) ? 1 : 0;
    }
    __syncthreads();
    if (tid < 22) {
        int m = tid;
        if (m < 21) {
            float p = 1.0f;
            for (int j = 3; j <= m; j++) p *= g_w01[2 * 21 + j].x;
            g_invP2[m] = (m >= 2) ? (1.0f / p) : 0.0f;
            float pm1 = (m >= 3) ? p / g_w01[2 * 21 + m].x : 0.0f;
            g_g3[m] = (m >= 4) ? g_w01[3 * 21 + m].y * pm1 : 0.0f;
        } else {
            g_invP2[21] = 0.0f;
        }
    }
}

__global__ __launch_bounds__(THREADS, 14)
void pc_kernel(const unsigned char* __restrict__ xb,
               float* __restrict__ out,
               int B)
{
    __shared__ float2   s_w01[9 * 21];
    __shared__ float    s_g3[21];
    __shared__ unsigned s_bal[WARPS][24];

    const int tid    = threadIdx.x;
    const int lane   = tid & 31;
    const int warpId = tid >> 5;
    const int elem4  = g_elem4;

    const int warpRow = blockIdx.x * ROWS_PER_BLOCK + warpId * (32 * TILES);

    // ---- 1. masks first (ballot transpose; only warp-scope sync) ----
    unsigned mask[TILES];

    if (elem4) {
        const unsigned* xw = reinterpret_cast<const unsigned*>(xb);
        const int wTotal = B * 20;
        #pragma unroll
        for (int t = 0; t < TILES; t++) {
            const int tileRow = warpRow + t * 32;
            const int wbase = tileRow * 20;
            if (tileRow + 32 <= B) {
                #pragma unroll
                for (int j = 0; j < 20; j++) {
                    unsigned w = xw[wbase + j * 32 + lane];
                    unsigned bal = __ballot_sync(0xFFFFFFFFu, w != 0u);
                    if (lane == 0) s_bal[warpId][j] = bal;
                }
            } else {
                #pragma unroll
                for (int j = 0; j < 20; j++) {
                    int idx = wbase + j * 32 + lane;
                    unsigned w = (idx < wTotal) ? xw[idx] : 0u;
                    unsigned bal = __ballot_sync(0xFFFFFFFFu, w != 0u);
                    if (lane == 0) s_bal[warpId][j] = bal;
                }
            }
            __syncwarp();
            int pos = 20 * lane;
            unsigned lo = s_bal[warpId][pos >> 5];
            unsigned hi = s_bal[warpId][(pos >> 5) + 1];
            mask[t] = __funnelshift_r(lo, hi, pos & 31) & 0xFFFFFu;
            __syncwarp();
        }
    } else {
        #pragma unroll
        for (int t = 0; t < TILES; t++) {
            int row = warpRow + t * 32 + lane;
            unsigned mres = 0;
            if (row < B) {
                const unsigned* p = reinterpret_cast<const unsigned*>(xb + (size_t)row * 20);
                #pragma unroll
                for (int j = 0; j < 5; j++) {
                    unsigned b = p[j] & 0x01010101u;
                    unsigned nib = ((b * 0x01020408u) >> 24) & 0xFu;
                    mres |= nib << (4 * j);
                }
            }
            mask[t] = mres;
        }
    }

    // ---- 2. table copy (overlaps with mask loads in flight) ----
    for (int i = tid; i < 9 * 21; i += THREADS) s_w01[i] = g_w01[i];
    if (tid < 21) s_g3[tid] = g_g3[tid];

    // ---- 3. per-row leaf/k2 collapse via __ldg (no smem dependency) ----
    float cc[TILES];
    unsigned Q[TILES];
    #pragma unroll
    for (int r = 0; r < TILES; r++) {
        unsigned M = mask[r];
        unsigned rem = M & (M - 1);
        int mst;
        float v;
        if (rem != 0u) {
            int p1 = __ffs(M) - 1;
            int p2 = __ffs(rem) - 1;
            mst = p2 + 1;
            bool pf2 = (M & 3u) == 3u;
            v = pf2 ? 1.0f : __ldg(&((const float*)g_w01)[(2 * 21 + mst) * 2 + 1])
                           * __ldg(&g_wsm[p2 * 32 + p1]);
        } else {
            mst = 21;
            v = 0.0f;
        }
        cc[r] = v * __ldg(&g_invP2[mst]);
        Q[r]  = M & (0xFFFFFFFFu << mst);
    }

    __syncthreads();

    // ---- 4. column-sweep DP, levels k=3..8 ----
    float S[TILES][KMAX - 2];
    #pragma unroll
    for (int r = 0; r < TILES; r++)
        #pragma unroll
        for (int k = 0; k < KMAX - 2; k++) S[r][k] = 0.0f;

    #pragma unroll
    for (int m = 1; m <= NCOL; m++) {
        unsigned bit[TILES], qb[TILES];
        #pragma unroll
        for (int r = 0; r < TILES; r++) {
            bit[r] = (mask[r] >> (m - 1)) & 1u;
            qb[r]  = (Q[r]    >> (m - 1)) & 1u;
        }
        #pragma unroll
        for (int k = KMAX; k >= 4; k--) {
            if (k > m) continue;                    // folds at compile time
            if (k == m) {
                const unsigned km = (1u << k) - 1u;
                #pragma unroll
                for (int r = 0; r < TILES; r++)
                    S[r][k - 3] = ((mask[r] & km) == km) ? 1.0f : 0.0f;
            } else {
                const float2 w = s_w01[k * 21 + m];
                #pragma unroll
                for (int r = 0; r < TILES; r++) {
                    float u = w.x * S[r][k - 3];
                    S[r][k - 3] = bit[r] ? fmaf(w.y, S[r][k - 4], u) : u;
                }
            }
        }
        if (m == 3) {
            #pragma unroll
            for (int r = 0; r < TILES; r++)
                S[r][0] = ((mask[r] & 7u) == 7u) ? 1.0f : 0.0f;
        } else if (m > 3) {
            const float w03 = s_w01[3 * 21 + m].x;
            const float g3m = s_g3[m];
            #pragma unroll
            for (int r = 0; r < TILES; r++) {
                float u = w03 * S[r][0];
                S[r][0] = qb[r] ? fmaf(cc[r], g3m, u) : u;
            }
        }
    }

    #pragma unroll
    for (int t = 0; t < TILES; t++) {
        int row = warpRow + t * 32 + lane;
        if (row < B) out[row] = S[t][KMAX - 3];
    }
}

extern "C" void kernel_launch(void* const* d_in, const int* in_sizes, int n_in,
                              void* d_out, int out_size)
{
    const unsigned char* x = (const unsigned char*)d_in[0];
    const float* Wleaf = (const float*)d_in[1];
    const float* W2 = (const float*)d_in[2];
    float* out = (float*)d_out;

    const int B = in_sizes[0] / NCOL;
    const int blocks = (B + ROWS_PER_BLOCK - 1) / ROWS_PER_BLOCK;

    prep_kernel<<<1, 736>>>(x, Wleaf, W2);
    pc_kernel<<<blocks, THREADS>>>(x, out, B);
}

// round 11
// speedup vs baseline: 1.5227x; 1.1253x over previous
#include <cuda_runtime.h>
#include <cstdint>

// naivePC: DP over (k,m) lattice, K=8, N=20.
// Transformed DP: S~(k,m) = S(k,m)/P_k[m], P_k[m] = prod_{j=k+1..m} w0_k[j], P_k[k]=1.
//   S~(k,m) = S~(k,m-1) + g_k[m]*x_{m-1}*S~(k-1,m-1),  g_k[m]=w1_k[m]*P_{k-1}[m-1]/P_k[m]
// => one predicated FFMA per (row, level, column). Output = S~(8,20)*P_8[20].
// Leaf/k2 collapse (validated): S~2(m) = cc (constant) for m>=mstart=p2+1,
//   cc = v*invP2[mstart], v = w1_2[mstart]*wsm[p2][p1] (or 1 if bits 0,1 set);
//   k=3 update: @(Q bit) S~3 += g3t[m]*cc, Q = mask & (~0<<mstart).

#define NCOL 20
#define KMAX 8
#define TILES 2
#define THREADS 128
#define WARPS (THREADS / 32)
#define ROWS_PER_BLOCK (THREADS * TILES)   // 256

__device__ float  g_wsm[21 * 32];
__device__ float2 g_w01[9 * 21];
__device__ float  g_invP2[22];
__device__ float4 g_gA[21];    // (g3t, g4, g5, g6)
__device__ float2 g_gB[21];    // (g7, g8)
__device__ float  g_scale;     // P_8[20]
__device__ int    g_elem4;

__global__ void prep_kernel(const unsigned char* __restrict__ xb,
                            const float* __restrict__ Wleaf,
                            const float* __restrict__ W2)
{
    __shared__ float sP[9][21];   // P_k[m], k=2..8

    const int tid  = threadIdx.x;
    const int lane = tid & 31;
    const int wid  = tid >> 5;

    // ---- wsm: one warp per m, shuffle reductions ----
    if (wid < 21) {
        int m = wid;
        float v = (lane < m) ? Wleaf[m * 20 + lane] : -1e30f;
        float mx = v;
        #pragma unroll
        for (int o = 16; o > 0; o >>= 1) mx = fmaxf(mx, __shfl_xor_sync(0xFFFFFFFFu, mx, o));
        float e = (lane < m) ? expf(v - mx) : 0.0f;
        float Z = e;
        #pragma unroll
        for (int o = 16; o > 0; o >>= 1) Z += __shfl_xor_sync(0xFFFFFFFFu, Z, o);
        float inv = (m > 0) ? (1.0f / Z) : 0.0f;
        g_wsm[m * 32 + lane] = e * inv;
    }
    // ---- w2 softmax: 189 pairs ----
    if (tid < 9 * 21) {
        float a = W2[tid * 2 + 0];
        float b = W2[tid * 2 + 1];
        float mx = fmaxf(a, b);
        float e0 = expf(a - mx), e1 = expf(b - mx);
        float inv = 1.0f / (e0 + e1);
        g_w01[tid] = make_float2(e0 * inv, e1 * inv);
    }
    // ---- dtype detection (warp 21) ----
    if (wid == 21) {
        unsigned w = reinterpret_cast<const unsigned*>(xb)[lane];
        unsigned gt1 = __ballot_sync(0xFFFFFFFFu, (w & 0xFEFEFEFEu) != 0u);
        unsigned hi  = __ballot_sync(0xFFFFFFFFu, (w & 0xFFFFFF00u) != 0u);
        if (lane == 0) g_elem4 = (gt1 != 0u || hi == 0u) ? 1 : 0;
    }
    __syncthreads();

    // ---- decay prefix products P_k[m] ----
    if (tid >= 2 && tid <= 8) {
        int k = tid;
        float p = 1.0f;
        for (int m = k; m <= 20; m++) {
            if (m > k) p *= g_w01[k * 21 + m].x;
            sP[k][m] = p;
        }
    }
    __syncthreads();

    // ---- transformed couplings ----
    if (tid < 21) {
        int m = tid;
        g_invP2[m] = (m >= 2) ? (1.0f / sP[2][m]) : 0.0f;
        float4 a;
        float2 b;
        a.x = (m >= 4) ? g_w01[3 * 21 + m].y * sP[2][m - 1] / sP[3][m] : 0.0f;
        a.y = (m >= 5) ? g_w01[4 * 21 + m].y * sP[3][m - 1] / sP[4][m] : 0.0f;
        a.z = (m >= 6) ? g_w01[5 * 21 + m].y * sP[4][m - 1] / sP[5][m] : 0.0f;
        a.w = (m >= 7) ? g_w01[6 * 21 + m].y * sP[5][m - 1] / sP[6][m] : 0.0f;
        b.x = (m >= 8) ? g_w01[7 * 21 + m].y * sP[6][m - 1] / sP[7][m] : 0.0f;
        b.y = (m >= 9) ? g_w01[8 * 21 + m].y * sP[7][m - 1] / sP[8][m] : 0.0f;
        g_gA[m] = a;
        g_gB[m] = b;
    }
    if (tid == 21) { g_invP2[21] = 0.0f; g_scale = sP[8][20]; }
}

__global__ __launch_bounds__(THREADS, 14)
void pc_kernel(const unsigned char* __restrict__ xb,
               float* __restrict__ out,
               int B)
{
    __shared__ float4   s_gA[21];
    __shared__ float2   s_gB[21];
    __shared__ unsigned s_bal[WARPS][24];

    const int tid    = threadIdx.x;
    const int lane   = tid & 31;
    const int warpId = tid >> 5;
    const int elem4  = g_elem4;

    const int warpRow = blockIdx.x * ROWS_PER_BLOCK + warpId * (32 * TILES);

    // ---- 1. masks first (ballot transpose; warp-scope sync only) ----
    unsigned mask[TILES];

    if (elem4) {
        const unsigned* xw = reinterpret_cast<const unsigned*>(xb);
        const int wTotal = B * 20;
        #pragma unroll
        for (int t = 0; t < TILES; t++) {
            const int tileRow = warpRow + t * 32;
            const int wbase = tileRow * 20;
            if (tileRow + 32 <= B) {
                #pragma unroll
                for (int j = 0; j < 20; j++) {
                    unsigned w = xw[wbase + j * 32 + lane];
                    unsigned bal = __ballot_sync(0xFFFFFFFFu, w != 0u);
                    if (lane == 0) s_bal[warpId][j] = bal;
                }
            } else {
                #pragma unroll
                for (int j = 0; j < 20; j++) {
                    int idx = wbase + j * 32 + lane;
                    unsigned w = (idx < wTotal) ? xw[idx] : 0u;
                    unsigned bal = __ballot_sync(0xFFFFFFFFu, w != 0u);
                    if (lane == 0) s_bal[warpId][j] = bal;
                }
            }
            __syncwarp();
            int pos = 20 * lane;
            unsigned lo = s_bal[warpId][pos >> 5];
            unsigned hi = s_bal[warpId][(pos >> 5) + 1];
            mask[t] = __funnelshift_r(lo, hi, pos & 31) & 0xFFFFFu;
            __syncwarp();
        }
    } else {
        #pragma unroll
        for (int t = 0; t < TILES; t++) {
            int row = warpRow + t * 32 + lane;
            unsigned mres = 0;
            if (row < B) {
                const unsigned* p = reinterpret_cast<const unsigned*>(xb + (size_t)row * 20);
                #pragma unroll
                for (int j = 0; j < 5; j++) {
                    unsigned b = p[j] & 0x01010101u;
                    unsigned nib = ((b * 0x01020408u) >> 24) & 0xFu;
                    mres |= nib << (4 * j);
                }
            }
            mask[t] = mres;
        }
    }

    // ---- 2. table copy (overlaps in-flight loads) ----
    if (tid < 21) s_gA[tid] = g_gA[tid];
    else if (tid >= 32 && tid < 32 + 21) s_gB[tid - 32] = g_gB[tid - 32];

    // ---- 3. per-row leaf/k2 collapse (global __ldg, no smem dependency) ----
    float cc[TILES];
    unsigned Q[TILES];
    #pragma unroll
    for (int r = 0; r < TILES; r++) {
        unsigned M = mask[r];
        unsigned rem = M & (M - 1);
        int mst;
        float v;
        if (rem != 0u) {
            int p1 = __ffs(M) - 1;
            int p2 = __ffs(rem) - 1;
            mst = p2 + 1;
            bool pf2 = (M & 3u) == 3u;
            v = pf2 ? 1.0f : __ldg(&((const float*)g_w01)[(2 * 21 + mst) * 2 + 1])
                           * __ldg(&g_wsm[p2 * 32 + p1]);
        } else {
            mst = 21;
            v = 0.0f;
        }
        cc[r] = v * __ldg(&g_invP2[mst]);
        Q[r]  = M & (0xFFFFFFFFu << mst);
    }
    const float scale = __ldg(&g_scale);

    __syncthreads();

    // ---- 4. column-sweep DP in transformed space: 1 predicated FFMA/level ----
    float S[TILES][KMAX - 2];   // S[r][k-3] = S~(k,.)
    #pragma unroll
    for (int r = 0; r < TILES; r++)
        #pragma unroll
        for (int k = 0; k < KMAX - 2; k++) S[r][k] = 0.0f;

    #pragma unroll
    for (int m = 1; m <= NCOL; m++) {
        const unsigned mbit = 1u << (m - 1);
        const float4 ga = s_gA[m];
        const float2 gb = s_gB[m];

        #pragma unroll
        for (int k = KMAX; k >= 4; k--) {
            if (k > m) continue;                    // folds at compile time
            if (k == m) {
                const unsigned km = (1u << k) - 1u;
                #pragma unroll
                for (int r = 0; r < TILES; r++)
                    S[r][k - 3] = ((mask[r] & km) == km) ? 1.0f : 0.0f;
            } else {
                const float g = (k == 4) ? ga.y : (k == 5) ? ga.z : (k == 6) ? ga.w
                              : (k == 7) ? gb.x : gb.y;
                #pragma unroll
                for (int r = 0; r < TILES; r++)
                    S[r][k - 3] = (mask[r] & mbit) ? fmaf(g, S[r][k - 4], S[r][k - 3])
                                                   : S[r][k - 3];
            }
        }
        if (m == 3) {
            #pragma unroll
            for (int r = 0; r < TILES; r++)
                S[r][0] = ((mask[r] & 7u) == 7u) ? 1.0f : 0.0f;
        } else if (m > 3) {
            #pragma unroll
            for (int r = 0; r < TILES; r++)
                S[r][0] = (Q[r] & mbit) ? fmaf(ga.x, cc[r], S[r][0]) : S[r][0];
        }
    }

    // ---- coalesced store ----
    #pragma unroll
    for (int t = 0; t < TILES; t++) {
        int row = warpRow + t * 32 + lane;
        if (row < B) out[row] = S[t][KMAX - 3] * scale;
    }
}

extern "C" void kernel_launch(void* const* d_in, const int* in_sizes, int n_in,
                              void* d_out, int out_size)
{
    const unsigned char* x = (const unsigned char*)d_in[0];
    const float* Wleaf = (const float*)d_in[1];
    const float* W2 = (const float*)d_in[2];
    float* out = (float*)d_out;

    const int B = in_sizes[0] / NCOL;
    const int blocks = (B + ROWS_PER_BLOCK - 1) / ROWS_PER_BLOCK;

    prep_kernel<<<1, 736>>>(x, Wleaf, W2);
    pc_kernel<<<blocks, THREADS>>>(x, out, B);
}